// round 1
// baseline (speedup 1.0000x reference)
#include <cuda_runtime.h>
#include <cstdint>
#include <cstddef>

// ============================================================================
// LSTM: x (32,512,1024), h0 (32,1024), Wx (1024,4096), Wh (1024,4096), b (4096)
// out (32,512,1024) fp32.
// Phase 1: g_xproj = x @ Wx + b   (tf32 mma.sync, 128x128x16 pipeline)
// Phase 2: 512 sequential step kernels, each: preact = xproj_t + h_{t-1} @ Wh,
//          gates -> c,h update. Kernel boundary provides the global sync.
// ============================================================================

#define DI __device__ __forceinline__

DI uint32_t smem_u32(const void* p) { return (uint32_t)__cvta_generic_to_shared(p); }

DI void cp16(const void* smem_dst, const void* gsrc) {
    asm volatile("cp.async.ca.shared.global [%0], [%1], 16;"
                 :: "r"(smem_u32(smem_dst)), "l"(gsrc));
}
DI void cp_commit() { asm volatile("cp.async.commit_group;"); }
DI void cp_wait0()  { asm volatile("cp.async.wait_group 0;"); }

DI uint32_t f2tf32(float f) {
    uint32_t u;
    asm("cvt.rna.tf32.f32 %0, %1;" : "=r"(u) : "f"(f));
    return u;
}

DI void mma_tf32(float* c, const uint32_t* a, const uint32_t* b) {
    asm volatile(
        "mma.sync.aligned.m16n8k8.row.col.f32.tf32.tf32.f32 "
        "{%0,%1,%2,%3}, {%4,%5,%6,%7}, {%8,%9}, {%0,%1,%2,%3};"
        : "+f"(c[0]), "+f"(c[1]), "+f"(c[2]), "+f"(c[3])
        : "r"(a[0]), "r"(a[1]), "r"(a[2]), "r"(a[3]), "r"(b[0]), "r"(b[1]));
}

// Scratch (allocation-free rule: __device__ globals)
__device__ float g_xproj[16384 * 4096];   // 256 MB: (N*T, 4H)
__device__ float g_c[32 * 1024];          // cell state (re-init at t==0)

// ----------------------------------------------------------------------------
// Phase 1: xproj = X(16384x1024) @ Wx(1024x4096) + b
// Tile 128x128, BK=16, double-buffered cp.async, 8 warps, warp tile 64x32.
// ----------------------------------------------------------------------------
__global__ void __launch_bounds__(256) xproj_kernel(
    const float* __restrict__ X, const float* __restrict__ Wx,
    const float* __restrict__ bias)
{
    __shared__ float sA[2][128][20];   // [m][k], row pad 20 (16B-aligned, conflict-free frags)
    __shared__ float sB[2][16][136];   // [k][n], row pad 136

    const int tid   = threadIdx.x;
    const int mBase = blockIdx.y * 128;
    const int nBase = blockIdx.x * 128;

    auto load_stage = [&](int s, int k0) {
#pragma unroll
        for (int i = tid; i < 512; i += 256) {
            int r = i >> 2, c = (i & 3) << 2;
            cp16(&sA[s][r][c], X + (size_t)(mBase + r) * 1024 + k0 + c);
        }
#pragma unroll
        for (int i = tid; i < 512; i += 256) {
            int r = i >> 5, c = (i & 31) << 2;
            cp16(&sB[s][r][c], Wx + (size_t)(k0 + r) * 4096 + nBase + c);
        }
        cp_commit();
    };

    load_stage(0, 0);

    const int warp = tid >> 5, lane = tid & 31;
    const int wm = (warp >> 2) * 64, wn = (warp & 3) * 32;
    const int gid = lane >> 2, tig = lane & 3;

    float acc[4][4][4];
#pragma unroll
    for (int mi = 0; mi < 4; ++mi)
#pragma unroll
        for (int ni = 0; ni < 4; ++ni)
#pragma unroll
            for (int r = 0; r < 4; ++r) acc[mi][ni][r] = 0.f;

    for (int kt = 0; kt < 64; ++kt) {
        const int cur = kt & 1;
        cp_wait0();
        __syncthreads();
        if (kt < 63) load_stage(cur ^ 1, (kt + 1) * 16);

#pragma unroll
        for (int kk = 0; kk < 16; kk += 8) {
            uint32_t af[4][4], bf[4][2];
#pragma unroll
            for (int mi = 0; mi < 4; ++mi) {
                int r = wm + mi * 16 + gid;
                af[mi][0] = f2tf32(sA[cur][r][kk + tig]);
                af[mi][1] = f2tf32(sA[cur][r + 8][kk + tig]);
                af[mi][2] = f2tf32(sA[cur][r][kk + tig + 4]);
                af[mi][3] = f2tf32(sA[cur][r + 8][kk + tig + 4]);
            }
#pragma unroll
            for (int ni = 0; ni < 4; ++ni) {
                int cc = wn + ni * 8 + gid;
                bf[ni][0] = f2tf32(sB[cur][kk + tig][cc]);
                bf[ni][1] = f2tf32(sB[cur][kk + tig + 4][cc]);
            }
#pragma unroll
            for (int mi = 0; mi < 4; ++mi)
#pragma unroll
                for (int ni = 0; ni < 4; ++ni)
                    mma_tf32(acc[mi][ni], af[mi], bf[ni]);
        }
    }

    // Epilogue: += bias, store to g_xproj
#pragma unroll
    for (int mi = 0; mi < 4; ++mi) {
#pragma unroll
        for (int ni = 0; ni < 4; ++ni) {
            int row = mBase + wm + mi * 16 + gid;
            int col = nBase + wn + ni * 8 + tig * 2;
            float b0 = bias[col], b1 = bias[col + 1];
            float* p0 = g_xproj + (size_t)row * 4096 + col;
            p0[0] = acc[mi][ni][0] + b0;
            p0[1] = acc[mi][ni][1] + b1;
            float* p1 = g_xproj + (size_t)(row + 8) * 4096 + col;
            p1[0] = acc[mi][ni][2] + b0;
            p1[1] = acc[mi][ni][3] + b1;
        }
    }
}

// ----------------------------------------------------------------------------
// Phase 2: one step. Grid = 128 CTAs; CTA c owns h columns [8c, 8c+8) and the
// 32 gate columns {q*1024 + 8c + j : q in 0..3, j in 0..7}.
// preact(32x32) = h_prev(32x1024) @ Wh[:, G] ; 8 warps split-K (warp w owns
// k8-steps == w mod 8, full 32x32 tile -> no fragment duplication), partials
// reduced in smem, then gates/cell update + write h_t into d_out directly.
// ----------------------------------------------------------------------------
__global__ void __launch_bounds__(256) lstm_step_kernel(
    const float* __restrict__ Wh, const float* __restrict__ hprev,
    long hstride, float* __restrict__ out, int t)
{
    // 38912 B: mma buffers; reused for 33792 B of partials afterwards.
    __shared__ __align__(16) char raw[38912];
    float (*sH)[32][72]   = reinterpret_cast<float (*)[32][72]>(raw);            // 2 x 32x72
    float (*sW)[64][40]   = reinterpret_cast<float (*)[64][40]>(raw + 18432);    // 2 x 64x40
    float (*part)[32][33] = reinterpret_cast<float (*)[32][33]>(raw);            // 8 x 32x33

    const int tid = threadIdx.x;
    const int c8  = blockIdx.x * 8;

    auto load_stage = [&](int s, int k0) {
#pragma unroll
        for (int i = tid; i < 512; i += 256) {          // h chunk: 32 x 64
            int b = i >> 4, c = (i & 15) << 2;
            cp16(&sH[s][b][c], hprev + (size_t)b * hstride + k0 + c);
        }
#pragma unroll
        for (int i = tid; i < 512; i += 256) {          // Wh chunk: 64 x 32 (4 strided groups)
            int k = i >> 3, ii = i & 7;
            int q = ii >> 1, off = (ii & 1) << 2;
            cp16(&sW[s][k][q * 8 + off],
                 Wh + (size_t)(k0 + k) * 4096 + q * 1024 + c8 + off);
        }
        cp_commit();
    };

    load_stage(0, 0);

    const int warp = tid >> 5, lane = tid & 31;
    const int gid = lane >> 2, tig = lane & 3;
    const int kk = warp * 8;   // this warp's k8-step within each 64-chunk

    float acc[2][4][4];
#pragma unroll
    for (int mi = 0; mi < 2; ++mi)
#pragma unroll
        for (int ni = 0; ni < 4; ++ni)
#pragma unroll
            for (int r = 0; r < 4; ++r) acc[mi][ni][r] = 0.f;

    for (int ch = 0; ch < 16; ++ch) {
        const int cur = ch & 1;
        cp_wait0();
        __syncthreads();
        if (ch < 15) load_stage(cur ^ 1, (ch + 1) * 64);

        uint32_t af[2][4], bf[4][2];
#pragma unroll
        for (int mi = 0; mi < 2; ++mi) {
            int r = mi * 16 + gid;
            af[mi][0] = f2tf32(sH[cur][r][kk + tig]);
            af[mi][1] = f2tf32(sH[cur][r + 8][kk + tig]);
            af[mi][2] = f2tf32(sH[cur][r][kk + tig + 4]);
            af[mi][3] = f2tf32(sH[cur][r + 8][kk + tig + 4]);
        }
#pragma unroll
        for (int ni = 0; ni < 4; ++ni) {
            bf[ni][0] = f2tf32(sW[cur][kk + tig][ni * 8 + gid]);
            bf[ni][1] = f2tf32(sW[cur][kk + tig + 4][ni * 8 + gid]);
        }
#pragma unroll
        for (int mi = 0; mi < 2; ++mi)
#pragma unroll
            for (int ni = 0; ni < 4; ++ni)
                mma_tf32(acc[mi][ni], af[mi], bf[ni]);
    }

    __syncthreads();   // done reading sH/sW; safe to alias with partials

#pragma unroll
    for (int mi = 0; mi < 2; ++mi)
#pragma unroll
        for (int ni = 0; ni < 4; ++ni) {
            int r = mi * 16 + gid, c = ni * 8 + tig * 2;
            part[warp][r][c]         = acc[mi][ni][0];
            part[warp][r][c + 1]     = acc[mi][ni][1];
            part[warp][r + 8][c]     = acc[mi][ni][2];
            part[warp][r + 8][c + 1] = acc[mi][ni][3];
        }
    __syncthreads();

    // One thread per (batch b, h-col j): reduce 8 partials, add xproj, gates.
    const int b = tid >> 3, j = tid & 7;
    float pre[4];
#pragma unroll
    for (int q = 0; q < 4; ++q) {
        int c = q * 8 + j;
        float s = 0.f;
#pragma unroll
        for (int w = 0; w < 8; ++w) s += part[w][b][c];
        s += g_xproj[((size_t)b * 512 + t) * 4096 + q * 1024 + c8 + j];
        pre[q] = s;
    }
    float ig = 1.f / (1.f + expf(-pre[0]));
    float fg = 1.f / (1.f + expf(-pre[1]));
    float og = 1.f / (1.f + expf(-pre[2]));
    float gg = tanhf(pre[3]);

    const int ci = b * 1024 + c8 + j;
    float cold = (t == 0) ? 0.f : g_c[ci];
    float cn = fg * cold + ig * gg;
    g_c[ci] = cn;
    out[((size_t)b * 512 + t) * 1024 + c8 + j] = og * tanhf(cn);
}

// ----------------------------------------------------------------------------
extern "C" void kernel_launch(void* const* d_in, const int* in_sizes, int n_in,
                              void* d_out, int out_size)
{
    const float* x  = (const float*)d_in[0];   // (32,512,1024)
    const float* h0 = (const float*)d_in[1];   // (32,1024)
    const float* Wx = (const float*)d_in[2];   // (1024,4096)
    const float* Wh = (const float*)d_in[3];   // (1024,4096)
    const float* b  = (const float*)d_in[4];   // (4096,)
    float* out = (float*)d_out;                // (32,512,1024)

    dim3 gA(32, 128);                          // N/128 x M/128
    xproj_kernel<<<gA, 256>>>(x, Wx, b);

    for (int t = 0; t < 512; ++t) {
        const float* hp = (t == 0) ? h0 : (out + (size_t)(t - 1) * 1024);
        long hs = (t == 0) ? 1024L : (long)512 * 1024;
        lstm_step_kernel<<<128, 256>>>(Wh, hp, hs, out, t);
    }
}

// round 2
// speedup vs baseline: 1.4005x; 1.4005x over previous
#include <cuda_runtime.h>
#include <cstdint>
#include <cstddef>

// ============================================================================
// LSTM: x (32,512,1024), h0 (32,1024), Wx (1024,4096), Wh (1024,4096), b (4096)
// out (32,512,1024) fp32.
// Phase 1: g_xproj = x @ Wx + b   (tf32 mma.sync, 128x128x16 pipeline)
// Phase 2: ONE persistent kernel, 128 co-resident CTAs, Wh slice resident in
//          SMEM (tf32), h staged per step via cp.async, grid spin-barrier
//          between steps. Cell state in registers.
// ============================================================================

#define DI __device__ __forceinline__

DI uint32_t smem_u32(const void* p) { return (uint32_t)__cvta_generic_to_shared(p); }

DI void cp16(const void* smem_dst, const void* gsrc) {
    asm volatile("cp.async.ca.shared.global [%0], [%1], 16;"
                 :: "r"(smem_u32(smem_dst)), "l"(gsrc));
}
DI void cp_commit() { asm volatile("cp.async.commit_group;"); }
DI void cp_wait0()  { asm volatile("cp.async.wait_group 0;"); }

DI uint32_t f2tf32(float f) {
    uint32_t u;
    asm("cvt.rna.tf32.f32 %0, %1;" : "=r"(u) : "f"(f));
    return u;
}

DI unsigned ld_acq_gpu(const unsigned* p) {
    unsigned v;
    asm volatile("ld.acquire.gpu.u32 %0, [%1];" : "=r"(v) : "l"(p));
    return v;
}

DI void mma_tf32(float* c, const uint32_t* a, const uint32_t* b) {
    asm volatile(
        "mma.sync.aligned.m16n8k8.row.col.f32.tf32.tf32.f32 "
        "{%0,%1,%2,%3}, {%4,%5,%6,%7}, {%8,%9}, {%0,%1,%2,%3};"
        : "+f"(c[0]), "+f"(c[1]), "+f"(c[2]), "+f"(c[3])
        : "r"(a[0]), "r"(a[1]), "r"(a[2]), "r"(a[3]), "r"(b[0]), "r"(b[1]));
}

// Scratch (allocation-free rule: __device__ globals)
__device__ float g_xproj[16384 * 4096];   // 256 MB: (N*T, 4H)
__device__ unsigned g_count;
__device__ unsigned g_epoch;

// ----------------------------------------------------------------------------
// Phase 1: xproj = X(16384x1024) @ Wx(1024x4096) + b  (unchanged from R1)
// ----------------------------------------------------------------------------
__global__ void __launch_bounds__(256) xproj_kernel(
    const float* __restrict__ X, const float* __restrict__ Wx,
    const float* __restrict__ bias)
{
    __shared__ float sA[2][128][20];
    __shared__ float sB[2][16][136];

    const int tid   = threadIdx.x;
    const int mBase = blockIdx.y * 128;
    const int nBase = blockIdx.x * 128;

    auto load_stage = [&](int s, int k0) {
#pragma unroll
        for (int i = tid; i < 512; i += 256) {
            int r = i >> 2, c = (i & 3) << 2;
            cp16(&sA[s][r][c], X + (size_t)(mBase + r) * 1024 + k0 + c);
        }
#pragma unroll
        for (int i = tid; i < 512; i += 256) {
            int r = i >> 5, c = (i & 31) << 2;
            cp16(&sB[s][r][c], Wx + (size_t)(k0 + r) * 4096 + nBase + c);
        }
        cp_commit();
    };

    load_stage(0, 0);

    const int warp = tid >> 5, lane = tid & 31;
    const int wm = (warp >> 2) * 64, wn = (warp & 3) * 32;
    const int gid = lane >> 2, tig = lane & 3;

    float acc[4][4][4];
#pragma unroll
    for (int mi = 0; mi < 4; ++mi)
#pragma unroll
        for (int ni = 0; ni < 4; ++ni)
#pragma unroll
            for (int r = 0; r < 4; ++r) acc[mi][ni][r] = 0.f;

    for (int kt = 0; kt < 64; ++kt) {
        const int cur = kt & 1;
        cp_wait0();
        __syncthreads();
        if (kt < 63) load_stage(cur ^ 1, (kt + 1) * 16);

#pragma unroll
        for (int kk = 0; kk < 16; kk += 8) {
            uint32_t af[4][4], bf[4][2];
#pragma unroll
            for (int mi = 0; mi < 4; ++mi) {
                int r = wm + mi * 16 + gid;
                af[mi][0] = f2tf32(sA[cur][r][kk + tig]);
                af[mi][1] = f2tf32(sA[cur][r + 8][kk + tig]);
                af[mi][2] = f2tf32(sA[cur][r][kk + tig + 4]);
                af[mi][3] = f2tf32(sA[cur][r + 8][kk + tig + 4]);
            }
#pragma unroll
            for (int ni = 0; ni < 4; ++ni) {
                int cc = wn + ni * 8 + gid;
                bf[ni][0] = f2tf32(sB[cur][kk + tig][cc]);
                bf[ni][1] = f2tf32(sB[cur][kk + tig + 4][cc]);
            }
#pragma unroll
            for (int mi = 0; mi < 4; ++mi)
#pragma unroll
                for (int ni = 0; ni < 4; ++ni)
                    mma_tf32(acc[mi][ni], af[mi], bf[ni]);
        }
    }

#pragma unroll
    for (int mi = 0; mi < 4; ++mi) {
#pragma unroll
        for (int ni = 0; ni < 4; ++ni) {
            int row = mBase + wm + mi * 16 + gid;
            int col = nBase + wn + ni * 8 + tig * 2;
            float b0 = bias[col], b1 = bias[col + 1];
            float* p0 = g_xproj + (size_t)row * 4096 + col;
            p0[0] = acc[mi][ni][0] + b0;
            p0[1] = acc[mi][ni][1] + b1;
            float* p1 = g_xproj + (size_t)(row + 8) * 4096 + col;
            p1[0] = acc[mi][ni][2] + b0;
            p1[1] = acc[mi][ni][3] + b1;
        }
    }
}

// ----------------------------------------------------------------------------
// Barrier state init
// ----------------------------------------------------------------------------
__global__ void init_kernel() { g_count = 0u; g_epoch = 0u; }

// ----------------------------------------------------------------------------
// Phase 2: persistent LSTM recurrence.
// CTA c owns h cols [8c,8c+8) and gate cols {q*1024 + 8c + j}.
// SMEM: sWh (tf32, 1024x32, stride 40, resident whole kernel) = 160 KB
//       union{ sH double-buffer 2x32x136 , partials 8x32x36 }   =  36 KB
// 8 warps split-K (warp w owns k-cols [w*16, w*16+16) of each 128-chunk).
// One grid barrier per step; c-state in registers; h_t written to out.
// ----------------------------------------------------------------------------
static const int SWH_BYTES   = 1024 * 40 * 4;                  // 163840
static const int UNION_BYTES = 8 * 32 * 36 * 4;                // 36864 (>= 2*32*136*4)
static const int SMEM_BYTES  = SWH_BYTES + UNION_BYTES;        // 200704

__global__ void __launch_bounds__(256, 1) lstm_persist(
    const float* __restrict__ Wh, const float* __restrict__ h0,
    float* __restrict__ out)
{
    extern __shared__ __align__(16) char dyn[];
    uint32_t (*sWh)[40]   = reinterpret_cast<uint32_t (*)[40]>(dyn);
    float (*sH)[32][136]  = reinterpret_cast<float (*)[32][136]>(dyn + SWH_BYTES);
    float (*part)[32][36] = reinterpret_cast<float (*)[32][36]>(dyn + SWH_BYTES);

    const int tid = threadIdx.x;
    const int c8  = blockIdx.x * 8;

    // ---- One-time: load this CTA's Wh slice, pre-converted to tf32 ----
    for (int idx = tid; idx < 1024 * 32; idx += 256) {
        int row = idx >> 5, col = idx & 31;
        int q = col >> 3, jj = col & 7;
        sWh[row][col] = f2tf32(__ldg(Wh + (size_t)row * 4096 + q * 1024 + c8 + jj));
    }
    __syncthreads();

    const int warp = tid >> 5, lane = tid & 31;
    const int gid = lane >> 2, tig = lane & 3;
    const int b = tid >> 3, j = tid & 7;       // epilogue cell mapping
    const int kw = warp * 16;                  // this warp's k-cols in a chunk

    float creg = 0.f;

    for (int t = 0; t < 512; ++t) {
        const float* hp;
        size_t hstride;
        if (t == 0) { hp = h0;                           hstride = 1024; }
        else        { hp = out + (size_t)(t - 1) * 1024; hstride = (size_t)512 * 1024; }

        // Prefetch this thread's 4 xproj values (DRAM latency hidden by mma loop)
        const float* xpp = g_xproj + ((size_t)b * 512 + t) * 4096 + c8 + j;
        float xp0 = __ldg(xpp);
        float xp1 = __ldg(xpp + 1024);
        float xp2 = __ldg(xpp + 2048);
        float xp3 = __ldg(xpp + 3072);

        auto load_h = [&](int s, int k0) {
#pragma unroll
            for (int i = tid; i < 1024; i += 256) {
                int bb = i >> 5, cc = (i & 31) << 2;
                cp16(&sH[s][bb][cc], hp + (size_t)bb * hstride + k0 + cc);
            }
            cp_commit();
        };
        load_h(0, 0);

        float acc[2][4][4];
#pragma unroll
        for (int mi = 0; mi < 2; ++mi)
#pragma unroll
            for (int ni = 0; ni < 4; ++ni)
#pragma unroll
                for (int r = 0; r < 4; ++r) acc[mi][ni][r] = 0.f;

        for (int ch = 0; ch < 8; ++ch) {
            const int cur = ch & 1;
            cp_wait0();
            __syncthreads();
            if (ch < 7) load_h(cur ^ 1, (ch + 1) * 128);

#pragma unroll
            for (int sub = 0; sub < 2; ++sub) {
                const int kk = kw + sub * 8;       // col within 128-chunk
                const int kg = ch * 128 + kk;      // global k (Wh row)
                uint32_t af[2][4], bf[4][2];
#pragma unroll
                for (int mi = 0; mi < 2; ++mi) {
                    int r = mi * 16 + gid;
                    af[mi][0] = f2tf32(sH[cur][r][kk + tig]);
                    af[mi][1] = f2tf32(sH[cur][r + 8][kk + tig]);
                    af[mi][2] = f2tf32(sH[cur][r][kk + tig + 4]);
                    af[mi][3] = f2tf32(sH[cur][r + 8][kk + tig + 4]);
                }
#pragma unroll
                for (int ni = 0; ni < 4; ++ni) {
                    bf[ni][0] = sWh[kg + tig][ni * 8 + gid];
                    bf[ni][1] = sWh[kg + tig + 4][ni * 8 + gid];
                }
#pragma unroll
                for (int mi = 0; mi < 2; ++mi)
#pragma unroll
                    for (int ni = 0; ni < 4; ++ni)
                        mma_tf32(acc[mi][ni], af[mi], bf[ni]);
            }
        }

        __syncthreads();   // done with sH; safe to alias partials

#pragma unroll
        for (int mi = 0; mi < 2; ++mi)
#pragma unroll
            for (int ni = 0; ni < 4; ++ni) {
                int r = mi * 16 + gid, c = ni * 8 + tig * 2;
                part[warp][r][c]         = acc[mi][ni][0];
                part[warp][r][c + 1]     = acc[mi][ni][1];
                part[warp][r + 8][c]     = acc[mi][ni][2];
                part[warp][r + 8][c + 1] = acc[mi][ni][3];
            }
        __syncthreads();

        // Reduce partials + xproj, gates, cell update, write h_t
        float pre[4] = {xp0, xp1, xp2, xp3};
#pragma unroll
        for (int q = 0; q < 4; ++q) {
            int c = q * 8 + j;
            float s = 0.f;
#pragma unroll
            for (int w = 0; w < 8; ++w) s += part[w][b][c];
            pre[q] += s;
        }
        float ig = 1.f / (1.f + expf(-pre[0]));
        float fg = 1.f / (1.f + expf(-pre[1]));
        float og = 1.f / (1.f + expf(-pre[2]));
        float gg = tanhf(pre[3]);
        creg = fg * creg + ig * gg;
        out[((size_t)b * 512 + t) * 1024 + c8 + j] = og * tanhf(creg);

        // ---- Grid barrier: h_t visible to all CTAs before step t+1 ----
        __threadfence();
        __syncthreads();
        if (tid == 0) {
            const unsigned target = (unsigned)(t + 1);
            if (atomicAdd(&g_count, 1u) == 127u) {
                atomicExch(&g_count, 0u);
                __threadfence();
                atomicAdd(&g_epoch, 1u);
            } else {
                while (ld_acq_gpu(&g_epoch) < target) { }
            }
        }
        __syncthreads();
    }
}

// ----------------------------------------------------------------------------
extern "C" void kernel_launch(void* const* d_in, const int* in_sizes, int n_in,
                              void* d_out, int out_size)
{
    const float* x  = (const float*)d_in[0];   // (32,512,1024)
    const float* h0 = (const float*)d_in[1];   // (32,1024)
    const float* Wx = (const float*)d_in[2];   // (1024,4096)
    const float* Wh = (const float*)d_in[3];   // (1024,4096)
    const float* b  = (const float*)d_in[4];   // (4096,)
    float* out = (float*)d_out;                // (32,512,1024)

    cudaFuncSetAttribute(lstm_persist,
                         cudaFuncAttributeMaxDynamicSharedMemorySize, SMEM_BYTES);

    dim3 gA(32, 128);
    xproj_kernel<<<gA, 256>>>(x, Wx, b);
    init_kernel<<<1, 1>>>();
    lstm_persist<<<128, 256, SMEM_BYTES>>>(Wh, h0, out);
}